// round 1
// baseline (speedup 1.0000x reference)
#include <cuda_runtime.h>

// PolynomialADMRSolver — B=4096, N=32, D=1024, fp32.
// out[b,d] = mean_k( x^e_k ),  e = {2,3,5,7},  x = states[b,d] * (sum_n w[b,n]*nb[b,n,d] + valence[b])
//
// Pure HBM-streaming kernel: 512 MiB neighbor read dominates. One CTA per b,
// 256 threads x float4 covers D=1024. Coalesced 4KB loads per n-step.

static constexpr int B = 4096;
static constexpr int N = 32;
static constexpr int D = 1024;
static constexpr int VEC = 4;                 // float4
static constexpr int THREADS = D / VEC;       // 256

__global__ __launch_bounds__(THREADS)
void poly_admr_kernel(const float* __restrict__ states,
                      const float* __restrict__ neighbor_states,
                      const float* __restrict__ adjacency_weight,
                      const float* __restrict__ valence,
                      float* __restrict__ out)
{
    const int b = blockIdx.x;
    const int t = threadIdx.x;

    __shared__ float w[N];
    if (t < N) w[t] = adjacency_weight[(size_t)b * N + t];
    __syncthreads();

    const float v = __ldg(&valence[b]);

    const float4* nb = reinterpret_cast<const float4*>(
        neighbor_states + (size_t)b * N * D);

    float4 acc = make_float4(0.f, 0.f, 0.f, 0.f);

    #pragma unroll 8
    for (int n = 0; n < N; ++n) {
        const float4 x = nb[(size_t)n * THREADS + t];
        const float wn = w[n];
        acc.x = fmaf(wn, x.x, acc.x);
        acc.y = fmaf(wn, x.y, acc.y);
        acc.z = fmaf(wn, x.z, acc.z);
        acc.w = fmaf(wn, x.w, acc.w);
    }

    const float4 s = reinterpret_cast<const float4*>(
        states + (size_t)b * D)[t];

    float4 r;
    {
        float x = s.x * (acc.x + v);
        float x2 = x * x, x3 = x2 * x, x5 = x3 * x2, x7 = x5 * x2;
        r.x = 0.25f * (x2 + x3 + x5 + x7);
    }
    {
        float x = s.y * (acc.y + v);
        float x2 = x * x, x3 = x2 * x, x5 = x3 * x2, x7 = x5 * x2;
        r.y = 0.25f * (x2 + x3 + x5 + x7);
    }
    {
        float x = s.z * (acc.z + v);
        float x2 = x * x, x3 = x2 * x, x5 = x3 * x2, x7 = x5 * x2;
        r.z = 0.25f * (x2 + x3 + x5 + x7);
    }
    {
        float x = s.w * (acc.w + v);
        float x2 = x * x, x3 = x2 * x, x5 = x3 * x2, x7 = x5 * x2;
        r.w = 0.25f * (x2 + x3 + x5 + x7);
    }

    reinterpret_cast<float4*>(out + (size_t)b * D)[t] = r;
}

extern "C" void kernel_launch(void* const* d_in, const int* in_sizes, int n_in,
                              void* d_out, int out_size)
{
    const float* states            = (const float*)d_in[0];
    const float* neighbor_states   = (const float*)d_in[1];
    const float* adjacency_weight  = (const float*)d_in[2];
    const float* valence           = (const float*)d_in[3];
    float* out = (float*)d_out;

    poly_admr_kernel<<<B, THREADS>>>(states, neighbor_states,
                                     adjacency_weight, valence, out);
}